// round 12
// baseline (speedup 1.0000x reference)
#include <cuda_runtime.h>
#include <cstdint>

// Problem shape (fixed by the dataset)
#define CC    19
#define BATCH 8
#define HH    512
#define WW    512
#define HW    (HH * WW)          // 262144
#define NPIX  (BATCH * HW)       // 2097152

// Histogram-sort: 2048 bins. Deterministic worst-case loss error =
// 0.5/NBINS * sum(lovasz grad)=1 -> 2.44e-4 << 1e-3 tolerance (measured 1.3e-7).
#define NBINS 2048
#define NCHK  8                          // rank-chunks per class
#define CHKSZ (NBINS / NCHK)             // 256 bins per chunk

#define SCAT_BLOCKS 148
#define SCAT_THREADS 1024
#define SMEM_BYTES (CC * NBINS * 4)      // 155648 B packed (fg<<16 | cnt) histogram

// Static device scratch (no allocations allowed). Zero at module load;
// the pipeline self-cleans every call so graph replays start clean:
//   g_bins  : zeroed by the k_loss chunk block that owns each bin range
//   g_chunk, g_loss, g_ticket : zeroed by the ticket-elected final block
__device__ unsigned long long g_bins[CC * NBINS];   // packed (fg<<32 | cnt)
__device__ unsigned long long g_chunk[CC * NCHK];   // packed per-bin-group totals
__device__ long long          g_gts[CC];
__device__ double             g_loss[CC];
__device__ unsigned int       g_ticket;

// ---------------------------------------------------------------------------
// K1: fused softmax + error quantization + SMEM-privatized histogram.
// Hot loop unchanged from R10 (~38 us, near the stream+ATOMS floor). The
// flush additionally maintains packed per-256-bin-group totals in g_chunk so
// k_loss chunk blocks never read bins outside their own range (enables both
// full chunk parallelism and race-free self-cleaning).
// ---------------------------------------------------------------------------
__global__ void __launch_bounds__(SCAT_THREADS, 1)
k_scatter(const float* __restrict__ in, const int* __restrict__ tgt) {
    extern __shared__ unsigned int s_cnt[];          // [CC * NBINS]

    for (int i = threadIdx.x; i < CC * NBINS; i += SCAT_THREADS) s_cnt[i] = 0u;
    __syncthreads();

    const int stride = SCAT_BLOCKS * SCAT_THREADS;
    for (int t = blockIdx.x * SCAT_THREADS + threadIdx.x; t < NPIX; t += stride) {
        int b  = t >> 18;                 // t / HW
        int hw = t & (HW - 1);
        const float* base = in + (size_t)b * CC * HW + hw;

        float x[CC];
        float s = 0.f;
#pragma unroll
        for (int c = 0; c < CC; c++) {
            x[c] = __expf(base[(size_t)c * HW]);   // logits ~N(0,1): no overflow
            s += x[c];
        }
        float inv = __fdividef(1.0f, s);
        int lbl = tgt[t];

#pragma unroll
        for (int c = 0; c < CC; c++) {
            float p  = x[c] * inv;
            bool  fg = (c == lbl);
            float e  = fg ? (1.0f - p) : p;
            e = fmaxf(e, 0.0f);
            unsigned bin = (unsigned)(e * (float)NBINS);
            if (bin >= NBINS) bin = NBINS - 1;
            unsigned inc = 1u + ((unsigned)fg << 16);
            atomicAdd(&s_cnt[c * NBINS + bin], inc);
        }
    }
    __syncthreads();

    // flush nonzero bins into packed u64 global (fg<<32 | cnt) + group totals
    for (int i = threadIdx.x; i < CC * NBINS; i += SCAT_THREADS) {
        unsigned v = s_cnt[i];
        if (v) {
            unsigned long long pv =
                ((unsigned long long)(v >> 16) << 32) |
                 (unsigned long long)(v & 0xFFFFu);
            atomicAdd(&g_bins[i], pv);
            int c   = i >> 11;                       // i / NBINS
            int bin = i & (NBINS - 1);
            atomicAdd(&g_chunk[c * NCHK + (bin >> 8)], pv);
        }
    }
}

// ---------------------------------------------------------------------------
// K2: grid = CC*NCHK = 152 fully independent chunk blocks, 256 threads each.
// Block (c, ch) owns ranks [ch*256, (ch+1)*256); rank r -> bin NBINS-1-r,
// i.e. bin group k = NCHK-1-ch. Offset before the chunk = sum of groups
// k' > k; gts = (sum of all groups) >> 32 -- both from the 8 g_chunk entries,
// so the block touches ONLY its own 256 raw bins (and self-cleans them).
// Per nonempty bin, exact int64 numerator Lovasz-Jaccard step:
//   j1 - j0 = (i0*u1 - i1*u0)/(u0*u1), i = gts-f, u = gts+n-f; num exact in
// int64, all terms >= 0 -> FP32 divide safe; accumulate in double.
// Per-class combine via atomicAdd double; ticket-elected last block averages
// present classes, writes the scalar, and zeroes g_chunk/g_loss/g_ticket.
// ---------------------------------------------------------------------------
__global__ void __launch_bounds__(CHKSZ, 1) k_loss(float* __restrict__ out) {
    int c    = blockIdx.x / NCHK;
    int ch   = blockIdx.x - c * NCHK;
    int tid  = threadIdx.x;
    int lane = tid & 31;
    int wid  = tid >> 5;

    // chunk totals -> gts and rank-offset
    int k = NCHK - 1 - ch;                           // my bin group
    unsigned long long tot = 0, off = 0;
#pragma unroll
    for (int kk = 0; kk < NCHK; kk++) {
        unsigned long long v = g_chunk[c * NCHK + kk];
        tot += v;
        if (kk > k) off += v;
    }
    long long gts = (long long)(tot >> 32);

    // own bin (rank = ch*256 + tid -> bin), self-clean
    int bin = NBINS - 1 - (ch * CHKSZ + tid);
    unsigned long long mb = g_bins[c * NBINS + bin];
    g_bins[c * NBINS + bin] = 0ULL;

    // block exclusive scan of packed bins (warp shuffle + one smem stage)
    unsigned long long incl = mb;
#pragma unroll
    for (int d = 1; d < 32; d <<= 1) {
        unsigned long long v = __shfl_up_sync(0xffffffffu, incl, d);
        if (lane >= d) incl += v;
    }
    __shared__ unsigned long long wtot[8];
    if (lane == 31) wtot[wid] = incl;
    __syncthreads();
    unsigned long long woff = 0;
#pragma unroll
    for (int ww = 0; ww < 8; ww++)
        if (ww < wid) woff += wtot[ww];
    unsigned long long run = off + woff + incl - mb;     // exclusive prefix

    double acc = 0.0;
    if (gts > 0 && mb) {
        long long n0 = (long long)(unsigned)run;
        long long f0 = (long long)(unsigned)(run >> 32);
        unsigned long long run1 = run + mb;
        long long n1 = (long long)(unsigned)run1;
        long long f1 = (long long)(unsigned)(run1 >> 32);
        long long iv0 = gts - f0, u0 = gts + n0 - f0;
        long long iv1 = gts - f1, u1 = gts + n1 - f1;
        long long num = iv0 * u1 - iv1 * u0;             // exact in int64
        float fnum = (float)num;
        float fden = (float)u0 * (float)u1;
        float e    = ((float)bin + 0.5f) * (1.0f / (float)NBINS);
        acc = (double)(e * __fdividef(fnum, fden));
    }

    // block reduce (double): warp reduce -> smem -> warp0
    __shared__ double sred[8];
#pragma unroll
    for (int d = 16; d; d >>= 1) acc += __shfl_down_sync(0xffffffffu, acc, d);
    if (lane == 0) sred[wid] = acc;
    __syncthreads();
    if (tid == 0) {
        double a = 0.0;
#pragma unroll
        for (int ww = 0; ww < 8; ww++) a += sred[ww];
        if (a != 0.0) atomicAdd(&g_loss[c], a);
        g_gts[c] = gts;                  // all chunk blocks write same value
        __threadfence();
        unsigned tk = atomicAdd(&g_ticket, 1u);
        if (tk == CC * NCHK - 1) {       // last block finalizes + self-cleans
            __threadfence();
            double s = 0.0, np = 0.0;
            for (int kk = 0; kk < CC; kk++) {
                if (g_gts[kk] > 0) { s += g_loss[kk]; np += 1.0; }
            }
            out[0] = (float)(s / (np > 1.0 ? np : 1.0));
            for (int kk = 0; kk < CC; kk++) g_loss[kk] = 0.0;
            for (int kk = 0; kk < CC * NCHK; kk++) g_chunk[kk] = 0ULL;
            g_ticket = 0u;
        }
    }
}

// ---------------------------------------------------------------------------
extern "C" void kernel_launch(void* const* d_in, const int* in_sizes, int n_in,
                              void* d_out, int out_size) {
    const float* input  = (const float*)d_in[0];
    const int*   target = (const int*)d_in[1];
    float*       out    = (float*)d_out;

    // Allow >48KB dynamic shared memory for the privatized histogram.
    cudaFuncSetAttribute(k_scatter, cudaFuncAttributeMaxDynamicSharedMemorySize,
                         SMEM_BYTES);

    k_scatter<<<SCAT_BLOCKS, SCAT_THREADS, SMEM_BYTES>>>(input, target);
    k_loss<<<CC * NCHK, CHKSZ>>>(out);
}

// round 13
// speedup vs baseline: 19.0049x; 19.0049x over previous
#include <cuda_runtime.h>
#include <cstdint>

// Problem shape (fixed by the dataset)
#define CC    19
#define BATCH 8
#define HH    512
#define WW    512
#define HW    (HH * WW)          // 262144
#define NPIX  (BATCH * HW)       // 2097152

// Histogram-sort: 2048 bins. Deterministic worst-case loss error =
// 0.5/NBINS * sum(lovasz grad)=1 -> 2.44e-4 << 1e-3 tolerance (measured 1.3e-7).
#define NBINS 2048
#define NCHK  8                          // rank-chunks per class
#define CHKSZ (NBINS / NCHK)             // 256 bins per chunk
#define NCHUNKS (CC * NCHK)              // 152

#define SCAT_BLOCKS 148
#define SCAT_THREADS 1024
#define SMEM_BYTES (CC * NBINS * 4)      // 155648 B packed (fg<<16 | cnt) histogram

// Static device scratch (no allocations allowed). Zero at module load;
// the pipeline self-cleans every call so graph replays start clean:
//   g_bins  : zeroed by the k_loss chunk block that owns each bin range
//   g_chunk, g_loss, g_ticket : zeroed by the ticket-elected final block
__device__ unsigned long long g_bins[CC * NBINS];   // packed (fg<<32 | cnt)
__device__ unsigned long long g_chunk[NCHUNKS];     // packed per-bin-group totals
__device__ long long          g_gts[CC];
__device__ double             g_loss[CC];
__device__ unsigned int       g_ticket;

// ---------------------------------------------------------------------------
// K1: fused softmax + error quantization + SMEM-privatized histogram.
// Hot loop unchanged from R10 (~38 us, near the stream+ATOMS floor).
// Chunk totals are reduced IN SHARED MEMORY per block (warp-parallel sums of
// the 256 packed counters per chunk; packed u32 sum is overflow-safe since
// per-block cnt <= 14173 < 2^16 and fg_sum<<16 <= 9.3e8 < 2^32), then ONE
// widened u64 REDG per (chunk, block): 152*148 ~ 22.5K atomics, ~148 per
// address -- vs R12's 5.7M per-bin REDGs on 152 addresses (the 987us bug).
// ---------------------------------------------------------------------------
__global__ void __launch_bounds__(SCAT_THREADS, 1)
k_scatter(const float* __restrict__ in, const int* __restrict__ tgt) {
    extern __shared__ unsigned int s_cnt[];          // [CC * NBINS]

    for (int i = threadIdx.x; i < CC * NBINS; i += SCAT_THREADS) s_cnt[i] = 0u;
    __syncthreads();

    const int stride = SCAT_BLOCKS * SCAT_THREADS;
    for (int t = blockIdx.x * SCAT_THREADS + threadIdx.x; t < NPIX; t += stride) {
        int b  = t >> 18;                 // t / HW
        int hw = t & (HW - 1);
        const float* base = in + (size_t)b * CC * HW + hw;

        float x[CC];
        float s = 0.f;
#pragma unroll
        for (int c = 0; c < CC; c++) {
            x[c] = __expf(base[(size_t)c * HW]);   // logits ~N(0,1): no overflow
            s += x[c];
        }
        float inv = __fdividef(1.0f, s);
        int lbl = tgt[t];

#pragma unroll
        for (int c = 0; c < CC; c++) {
            float p  = x[c] * inv;
            bool  fg = (c == lbl);
            float e  = fg ? (1.0f - p) : p;
            e = fmaxf(e, 0.0f);
            unsigned bin = (unsigned)(e * (float)NBINS);
            if (bin >= NBINS) bin = NBINS - 1;
            unsigned inc = 1u + ((unsigned)fg << 16);
            atomicAdd(&s_cnt[c * NBINS + bin], inc);
        }
    }
    __syncthreads();

    // flush nonzero bins into packed u64 global (fg<<32 | cnt)
    for (int i = threadIdx.x; i < CC * NBINS; i += SCAT_THREADS) {
        unsigned v = s_cnt[i];
        if (v) atomicAdd(&g_bins[i],
                 ((unsigned long long)(v >> 16) << 32) |
                  (unsigned long long)(v & 0xFFFFu));
    }

    // per-block chunk totals: warp w handles chunks w, w+32, ...
    int lane = threadIdx.x & 31;
    int wid  = threadIdx.x >> 5;
    for (int ch = wid; ch < NCHUNKS; ch += 32) {
        const unsigned* p = s_cnt + ch * CHKSZ;
        unsigned sum = 0;
#pragma unroll
        for (int j = 0; j < CHKSZ / 32; j++) sum += p[j * 32 + lane];
#pragma unroll
        for (int d = 16; d; d >>= 1) sum += __shfl_down_sync(0xffffffffu, sum, d);
        if (lane == 0 && sum)
            atomicAdd(&g_chunk[ch],
                      ((unsigned long long)(sum >> 16) << 32) |
                       (unsigned long long)(sum & 0xFFFFu));
    }
}

// ---------------------------------------------------------------------------
// K2: grid = CC*NCHK = 152 fully independent chunk blocks, 256 threads each.
// Block (c, ch) owns ranks [ch*256, (ch+1)*256); rank r -> bin NBINS-1-r,
// i.e. bin group k = NCHK-1-ch. Offset before the chunk = sum of groups
// k' > k; gts = (sum of all groups) >> 32 -- both from the 8 g_chunk entries,
// so the block touches ONLY its own 256 raw bins (and self-cleans them).
// Per nonempty bin, exact int64 numerator Lovasz-Jaccard step:
//   j1 - j0 = (i0*u1 - i1*u0)/(u0*u1), i = gts-f, u = gts+n-f; num exact in
// int64, all terms >= 0 -> FP32 divide safe; accumulate in double.
// Per-class combine via atomicAdd double; ticket-elected last block averages
// present classes, writes the scalar, and zeroes g_chunk/g_loss/g_ticket.
// ---------------------------------------------------------------------------
__global__ void __launch_bounds__(CHKSZ, 1) k_loss(float* __restrict__ out) {
    int c    = blockIdx.x / NCHK;
    int ch   = blockIdx.x - c * NCHK;
    int tid  = threadIdx.x;
    int lane = tid & 31;
    int wid  = tid >> 5;

    // chunk totals -> gts and rank-offset
    int k = NCHK - 1 - ch;                           // my bin group
    unsigned long long tot = 0, off = 0;
#pragma unroll
    for (int kk = 0; kk < NCHK; kk++) {
        unsigned long long v = g_chunk[c * NCHK + kk];
        tot += v;
        if (kk > k) off += v;
    }
    long long gts = (long long)(tot >> 32);

    // own bin (rank = ch*256 + tid -> bin), self-clean
    int bin = NBINS - 1 - (ch * CHKSZ + tid);
    unsigned long long mb = g_bins[c * NBINS + bin];
    g_bins[c * NBINS + bin] = 0ULL;

    // block exclusive scan of packed bins (warp shuffle + one smem stage)
    unsigned long long incl = mb;
#pragma unroll
    for (int d = 1; d < 32; d <<= 1) {
        unsigned long long v = __shfl_up_sync(0xffffffffu, incl, d);
        if (lane >= d) incl += v;
    }
    __shared__ unsigned long long wtot[8];
    if (lane == 31) wtot[wid] = incl;
    __syncthreads();
    unsigned long long woff = 0;
#pragma unroll
    for (int ww = 0; ww < 8; ww++)
        if (ww < wid) woff += wtot[ww];
    unsigned long long run = off + woff + incl - mb;     // exclusive prefix

    double acc = 0.0;
    if (gts > 0 && mb) {
        long long n0 = (long long)(unsigned)run;
        long long f0 = (long long)(unsigned)(run >> 32);
        unsigned long long run1 = run + mb;
        long long n1 = (long long)(unsigned)run1;
        long long f1 = (long long)(unsigned)(run1 >> 32);
        long long iv0 = gts - f0, u0 = gts + n0 - f0;
        long long iv1 = gts - f1, u1 = gts + n1 - f1;
        long long num = iv0 * u1 - iv1 * u0;             // exact in int64
        float fnum = (float)num;
        float fden = (float)u0 * (float)u1;
        float e    = ((float)bin + 0.5f) * (1.0f / (float)NBINS);
        acc = (double)(e * __fdividef(fnum, fden));
    }

    // block reduce (double): warp reduce -> smem -> thread 0
    __shared__ double sred[8];
#pragma unroll
    for (int d = 16; d; d >>= 1) acc += __shfl_down_sync(0xffffffffu, acc, d);
    if (lane == 0) sred[wid] = acc;
    __syncthreads();
    if (tid == 0) {
        double a = 0.0;
#pragma unroll
        for (int ww = 0; ww < 8; ww++) a += sred[ww];
        if (a != 0.0) atomicAdd(&g_loss[c], a);
        g_gts[c] = gts;                  // all chunk blocks write same value
        __threadfence();
        unsigned tk = atomicAdd(&g_ticket, 1u);
        if (tk == CC * NCHK - 1) {       // last block finalizes + self-cleans
            __threadfence();
            double s = 0.0, np = 0.0;
            for (int kk = 0; kk < CC; kk++) {
                if (g_gts[kk] > 0) { s += g_loss[kk]; np += 1.0; }
            }
            out[0] = (float)(s / (np > 1.0 ? np : 1.0));
            for (int kk = 0; kk < CC; kk++) g_loss[kk] = 0.0;
            for (int kk = 0; kk < NCHUNKS; kk++) g_chunk[kk] = 0ULL;
            g_ticket = 0u;
        }
    }
}

// ---------------------------------------------------------------------------
extern "C" void kernel_launch(void* const* d_in, const int* in_sizes, int n_in,
                              void* d_out, int out_size) {
    const float* input  = (const float*)d_in[0];
    const int*   target = (const int*)d_in[1];
    float*       out    = (float*)d_out;

    // Allow >48KB dynamic shared memory for the privatized histogram.
    cudaFuncSetAttribute(k_scatter, cudaFuncAttributeMaxDynamicSharedMemorySize,
                         SMEM_BYTES);

    k_scatter<<<SCAT_BLOCKS, SCAT_THREADS, SMEM_BYTES>>>(input, target);
    k_loss<<<CC * NCHK, CHKSZ>>>(out);
}

// round 14
// speedup vs baseline: 20.1199x; 1.0587x over previous
#include <cuda_runtime.h>
#include <cstdint>

// Problem shape (fixed by the dataset)
#define CC    19
#define BATCH 8
#define HH    512
#define WW    512
#define HW    (HH * WW)          // 262144
#define NPIX  (BATCH * HW)       // 2097152
#define NPAIR (NPIX / 2)         // 1048576 pixel pairs

// Histogram-sort: 2048 bins. Deterministic worst-case loss error =
// 0.5/NBINS * sum(lovasz grad)=1 -> 2.44e-4 << 1e-3 tolerance (measured 1.3e-7).
#define NBINS 2048
#define NCHK  8                          // rank-chunks per class
#define CHKSZ (NBINS / NCHK)             // 256 bins per chunk
#define NCHUNKS (CC * NCHK)              // 152

#define SCAT_BLOCKS 148
#define SCAT_THREADS 1024
#define SMEM_BYTES (CC * NBINS * 4)      // 155648 B packed (fg<<16 | cnt) histogram

// Static device scratch (no allocations allowed). Zero at module load;
// the pipeline self-cleans every call so graph replays start clean:
//   g_bins  : zeroed by the k_loss chunk block that owns each bin range
//   g_chunk, g_loss, g_ticket : zeroed by the ticket-elected final block
__device__ unsigned long long g_bins[CC * NBINS];   // packed (fg<<32 | cnt)
__device__ unsigned long long g_chunk[NCHUNKS];     // packed per-bin-group totals
__device__ long long          g_gts[CC];
__device__ double             g_loss[CC];
__device__ unsigned int       g_ticket;

// ---------------------------------------------------------------------------
// K1: fused softmax + error quantization + SMEM-privatized histogram.
// PIXEL-PAIRED: each thread handles 2 consecutive pixels per iteration via
// float2 loads (hw stays even -> 8B-aligned, never crosses the batch row):
// 19 LDG.64 replace 38 LDG.32 (same bytes, same coalescing), halving LDG
// issue and loop overhead per pixel and doubling per-thread MLP. Atomic
// count unchanged (irreducible core). Chunk totals reduced in SMEM, ONE
// widened u64 REDG per (chunk, block) -- the R13 fix for the R12 contention.
// ---------------------------------------------------------------------------
__global__ void __launch_bounds__(SCAT_THREADS, 1)
k_scatter(const float* __restrict__ in, const int* __restrict__ tgt) {
    extern __shared__ unsigned int s_cnt[];          // [CC * NBINS]

    for (int i = threadIdx.x; i < CC * NBINS; i += SCAT_THREADS) s_cnt[i] = 0u;
    __syncthreads();

    const int stride = SCAT_BLOCKS * SCAT_THREADS;
    for (int i = blockIdx.x * SCAT_THREADS + threadIdx.x; i < NPAIR; i += stride) {
        int t  = i * 2;                  // even pixel index
        int b  = t >> 18;                // t / HW
        int hw = t & (HW - 1);           // even -> hw+1 < HW
        const float2* base2 =
            reinterpret_cast<const float2*>(in + (size_t)b * CC * HW + hw);

        float x0[CC], x1[CC];
        float s0 = 0.f, s1 = 0.f;
#pragma unroll
        for (int c = 0; c < CC; c++) {
            float2 v = base2[c * (HW / 2)];
            x0[c] = __expf(v.x);         // logits ~N(0,1): no overflow
            x1[c] = __expf(v.y);
            s0 += x0[c];
            s1 += x1[c];
        }
        float inv0 = __fdividef(1.0f, s0);
        float inv1 = __fdividef(1.0f, s1);
        int2 lbl = reinterpret_cast<const int2*>(tgt)[i];

#pragma unroll
        for (int c = 0; c < CC; c++) {
            // pixel 0
            float p0  = x0[c] * inv0;
            bool  fg0 = (c == lbl.x);
            float e0  = fg0 ? (1.0f - p0) : p0;
            e0 = fmaxf(e0, 0.0f);
            unsigned bin0 = (unsigned)(e0 * (float)NBINS);
            if (bin0 >= NBINS) bin0 = NBINS - 1;
            atomicAdd(&s_cnt[c * NBINS + bin0], 1u + ((unsigned)fg0 << 16));
            // pixel 1
            float p1  = x1[c] * inv1;
            bool  fg1 = (c == lbl.y);
            float e1  = fg1 ? (1.0f - p1) : p1;
            e1 = fmaxf(e1, 0.0f);
            unsigned bin1 = (unsigned)(e1 * (float)NBINS);
            if (bin1 >= NBINS) bin1 = NBINS - 1;
            atomicAdd(&s_cnt[c * NBINS + bin1], 1u + ((unsigned)fg1 << 16));
        }
    }
    __syncthreads();

    // flush nonzero bins into packed u64 global (fg<<32 | cnt)
    for (int i = threadIdx.x; i < CC * NBINS; i += SCAT_THREADS) {
        unsigned v = s_cnt[i];
        if (v) atomicAdd(&g_bins[i],
                 ((unsigned long long)(v >> 16) << 32) |
                  (unsigned long long)(v & 0xFFFFu));
    }

    // per-block chunk totals: warp w handles chunks w, w+32, ...
    // (packed u32 sum overflow-safe: per-block cnt <= 14173 < 2^16,
    //  fg_sum<<16 <= 9.3e8 < 2^32)
    int lane = threadIdx.x & 31;
    int wid  = threadIdx.x >> 5;
    for (int ch = wid; ch < NCHUNKS; ch += 32) {
        const unsigned* p = s_cnt + ch * CHKSZ;
        unsigned sum = 0;
#pragma unroll
        for (int j = 0; j < CHKSZ / 32; j++) sum += p[j * 32 + lane];
#pragma unroll
        for (int d = 16; d; d >>= 1) sum += __shfl_down_sync(0xffffffffu, sum, d);
        if (lane == 0 && sum)
            atomicAdd(&g_chunk[ch],
                      ((unsigned long long)(sum >> 16) << 32) |
                       (unsigned long long)(sum & 0xFFFFu));
    }
}

// ---------------------------------------------------------------------------
// K2: grid = CC*NCHK = 152 fully independent chunk blocks, 256 threads each.
// (unchanged from R13 -- measured 9.95 us.) Block (c, ch) owns ranks
// [ch*256, (ch+1)*256); rank r -> bin NBINS-1-r. Offset/gts come from the 8
// g_chunk entries, so the block touches ONLY its own 256 raw bins and
// self-cleans them race-free. Exact int64 numerator Lovasz-Jaccard step:
//   j1 - j0 = (i0*u1 - i1*u0)/(u0*u1), i = gts-f, u = gts+n-f; num exact in
// int64, all terms >= 0 -> FP32 divide safe; accumulate in double.
// Ticket-elected last block averages present classes and self-cleans state.
// ---------------------------------------------------------------------------
__global__ void __launch_bounds__(CHKSZ, 1) k_loss(float* __restrict__ out) {
    int c    = blockIdx.x / NCHK;
    int ch   = blockIdx.x - c * NCHK;
    int tid  = threadIdx.x;
    int lane = tid & 31;
    int wid  = tid >> 5;

    // chunk totals -> gts and rank-offset
    int k = NCHK - 1 - ch;                           // my bin group
    unsigned long long tot = 0, off = 0;
#pragma unroll
    for (int kk = 0; kk < NCHK; kk++) {
        unsigned long long v = g_chunk[c * NCHK + kk];
        tot += v;
        if (kk > k) off += v;
    }
    long long gts = (long long)(tot >> 32);

    // own bin (rank = ch*256 + tid -> bin), self-clean
    int bin = NBINS - 1 - (ch * CHKSZ + tid);
    unsigned long long mb = g_bins[c * NBINS + bin];
    g_bins[c * NBINS + bin] = 0ULL;

    // block exclusive scan of packed bins (warp shuffle + one smem stage)
    unsigned long long incl = mb;
#pragma unroll
    for (int d = 1; d < 32; d <<= 1) {
        unsigned long long v = __shfl_up_sync(0xffffffffu, incl, d);
        if (lane >= d) incl += v;
    }
    __shared__ unsigned long long wtot[8];
    if (lane == 31) wtot[wid] = incl;
    __syncthreads();
    unsigned long long woff = 0;
#pragma unroll
    for (int ww = 0; ww < 8; ww++)
        if (ww < wid) woff += wtot[ww];
    unsigned long long run = off + woff + incl - mb;     // exclusive prefix

    double acc = 0.0;
    if (gts > 0 && mb) {
        long long n0 = (long long)(unsigned)run;
        long long f0 = (long long)(unsigned)(run >> 32);
        unsigned long long run1 = run + mb;
        long long n1 = (long long)(unsigned)run1;
        long long f1 = (long long)(unsigned)(run1 >> 32);
        long long iv0 = gts - f0, u0 = gts + n0 - f0;
        long long iv1 = gts - f1, u1 = gts + n1 - f1;
        long long num = iv0 * u1 - iv1 * u0;             // exact in int64
        float fnum = (float)num;
        float fden = (float)u0 * (float)u1;
        float e    = ((float)bin + 0.5f) * (1.0f / (float)NBINS);
        acc = (double)(e * __fdividef(fnum, fden));
    }

    // block reduce (double): warp reduce -> smem -> thread 0
    __shared__ double sred[8];
#pragma unroll
    for (int d = 16; d; d >>= 1) acc += __shfl_down_sync(0xffffffffu, acc, d);
    if (lane == 0) sred[wid] = acc;
    __syncthreads();
    if (tid == 0) {
        double a = 0.0;
#pragma unroll
        for (int ww = 0; ww < 8; ww++) a += sred[ww];
        if (a != 0.0) atomicAdd(&g_loss[c], a);
        g_gts[c] = gts;                  // all chunk blocks write same value
        __threadfence();
        unsigned tk = atomicAdd(&g_ticket, 1u);
        if (tk == CC * NCHK - 1) {       // last block finalizes + self-cleans
            __threadfence();
            double s = 0.0, np = 0.0;
            for (int kk = 0; kk < CC; kk++) {
                if (g_gts[kk] > 0) { s += g_loss[kk]; np += 1.0; }
            }
            out[0] = (float)(s / (np > 1.0 ? np : 1.0));
            for (int kk = 0; kk < CC; kk++) g_loss[kk] = 0.0;
            for (int kk = 0; kk < NCHUNKS; kk++) g_chunk[kk] = 0ULL;
            g_ticket = 0u;
        }
    }
}

// ---------------------------------------------------------------------------
extern "C" void kernel_launch(void* const* d_in, const int* in_sizes, int n_in,
                              void* d_out, int out_size) {
    const float* input  = (const float*)d_in[0];
    const int*   target = (const int*)d_in[1];
    float*       out    = (float*)d_out;

    // Allow >48KB dynamic shared memory for the privatized histogram.
    cudaFuncSetAttribute(k_scatter, cudaFuncAttributeMaxDynamicSharedMemorySize,
                         SMEM_BYTES);

    k_scatter<<<SCAT_BLOCKS, SCAT_THREADS, SMEM_BYTES>>>(input, target);
    k_loss<<<CC * NCHK, CHKSZ>>>(out);
}

// round 15
// speedup vs baseline: 20.6448x; 1.0261x over previous
#include <cuda_runtime.h>
#include <cstdint>

// Problem shape (fixed by the dataset)
#define CC    19
#define BATCH 8
#define HH    512
#define WW    512
#define HW    (HH * WW)          // 262144
#define NPIX  (BATCH * HW)       // 2097152
#define NPAIR (NPIX / 2)         // 1048576 pixel pairs

// Histogram-sort: 1024 bins. Deterministic worst-case loss error =
// 0.5/NBINS * sum(lovasz grad <= 1) = 4.9e-4 < 1e-3 tolerance; measured
// error at 2048 bins was 1.3e-7 (massive cancellation), expect ~1e-6 here.
#define NBINS 1024
#define NCHK  8                          // rank-chunks per class
#define CHKSZ (NBINS / NCHK)             // 128 bins per chunk
#define NCHUNKS (CC * NCHK)              // 152

#define SCAT_BLOCKS 148
#define SCAT_THREADS 1024
#define SMEM_BYTES (CC * NBINS * 4)      // 77824 B packed (fg<<16 | cnt) histogram

// Static device scratch (no allocations allowed). Zero at module load;
// the pipeline self-cleans every call so graph replays start clean:
//   g_bins  : zeroed by the k_loss chunk block that owns each bin range
//   g_chunk, g_loss, g_ticket : zeroed by the ticket-elected final block
__device__ unsigned long long g_bins[CC * NBINS];   // packed (fg<<32 | cnt)
__device__ unsigned long long g_chunk[NCHUNKS];     // packed per-bin-group totals
__device__ long long          g_gts[CC];
__device__ double             g_loss[CC];
__device__ unsigned int       g_ticket;

// ---------------------------------------------------------------------------
// K1: fused softmax + error quantization + SMEM-privatized histogram.
// Pixel-paired float2 loads (R14). NBINS halved to 1024: init loop, flush
// REDGs (5.8M -> 2.9M chip-wide) and chunk reduction all halve while the
// 40M hot-loop SMEM atomics are unchanged (bin counts stay contention-free).
// Chunk totals reduced in SMEM, ONE widened u64 REDG per (chunk, block).
// ---------------------------------------------------------------------------
__global__ void __launch_bounds__(SCAT_THREADS, 1)
k_scatter(const float* __restrict__ in, const int* __restrict__ tgt) {
    extern __shared__ unsigned int s_cnt[];          // [CC * NBINS]

    for (int i = threadIdx.x; i < CC * NBINS; i += SCAT_THREADS) s_cnt[i] = 0u;
    __syncthreads();

    const int stride = SCAT_BLOCKS * SCAT_THREADS;
    for (int i = blockIdx.x * SCAT_THREADS + threadIdx.x; i < NPAIR; i += stride) {
        int t  = i * 2;                  // even pixel index
        int b  = t >> 18;                // t / HW
        int hw = t & (HW - 1);           // even -> hw+1 < HW
        const float2* base2 =
            reinterpret_cast<const float2*>(in + (size_t)b * CC * HW + hw);

        float x0[CC], x1[CC];
        float s0 = 0.f, s1 = 0.f;
#pragma unroll
        for (int c = 0; c < CC; c++) {
            float2 v = base2[c * (HW / 2)];
            x0[c] = __expf(v.x);         // logits ~N(0,1): no overflow
            x1[c] = __expf(v.y);
            s0 += x0[c];
            s1 += x1[c];
        }
        float inv0 = __fdividef(1.0f, s0);
        float inv1 = __fdividef(1.0f, s1);
        int2 lbl = reinterpret_cast<const int2*>(tgt)[i];

#pragma unroll
        for (int c = 0; c < CC; c++) {
            // pixel 0
            float p0  = x0[c] * inv0;
            bool  fg0 = (c == lbl.x);
            float e0  = fg0 ? (1.0f - p0) : p0;
            e0 = fmaxf(e0, 0.0f);
            unsigned bin0 = (unsigned)(e0 * (float)NBINS);
            if (bin0 >= NBINS) bin0 = NBINS - 1;
            atomicAdd(&s_cnt[c * NBINS + bin0], 1u + ((unsigned)fg0 << 16));
            // pixel 1
            float p1  = x1[c] * inv1;
            bool  fg1 = (c == lbl.y);
            float e1  = fg1 ? (1.0f - p1) : p1;
            e1 = fmaxf(e1, 0.0f);
            unsigned bin1 = (unsigned)(e1 * (float)NBINS);
            if (bin1 >= NBINS) bin1 = NBINS - 1;
            atomicAdd(&s_cnt[c * NBINS + bin1], 1u + ((unsigned)fg1 << 16));
        }
    }
    __syncthreads();

    // flush nonzero bins into packed u64 global (fg<<32 | cnt)
    for (int i = threadIdx.x; i < CC * NBINS; i += SCAT_THREADS) {
        unsigned v = s_cnt[i];
        if (v) atomicAdd(&g_bins[i],
                 ((unsigned long long)(v >> 16) << 32) |
                  (unsigned long long)(v & 0xFFFFu));
    }

    // per-block chunk totals: warp w handles chunks w, w+32, ...
    // (packed u32 sum overflow-safe: per-block cnt <= 14170 < 2^16,
    //  fg_sum<<16 <= 9.3e8 < 2^32)
    int lane = threadIdx.x & 31;
    int wid  = threadIdx.x >> 5;
    for (int ch = wid; ch < NCHUNKS; ch += 32) {
        const unsigned* p = s_cnt + ch * CHKSZ;
        unsigned sum = 0;
#pragma unroll
        for (int j = 0; j < CHKSZ / 32; j++) sum += p[j * 32 + lane];
#pragma unroll
        for (int d = 16; d; d >>= 1) sum += __shfl_down_sync(0xffffffffu, sum, d);
        if (lane == 0 && sum)
            atomicAdd(&g_chunk[ch],
                      ((unsigned long long)(sum >> 16) << 32) |
                       (unsigned long long)(sum & 0xFFFFu));
    }
}

// ---------------------------------------------------------------------------
// K2: grid = CC*NCHK = 152 independent chunk blocks, 128 threads each.
// Launched with PDL (programmatic stream serialization): the grid spins up
// concurrently with k_scatter's tail; cudaGridDependencySynchronize() at
// entry enforces the full-completion dependency before any global read.
// Block (c, ch) owns ranks [ch*128, (ch+1)*128); rank r -> bin NBINS-1-r.
// Offset/gts come from the 8 g_chunk entries, so the block touches ONLY its
// own 128 raw bins and self-cleans them race-free. Exact int64 numerator
// Lovasz-Jaccard step: j1-j0 = (i0*u1 - i1*u0)/(u0*u1), i = gts-f,
// u = gts+n-f; num exact in int64, all terms >= 0 -> FP32 divide safe;
// accumulate in double. Ticket-elected last block averages present classes
// and self-cleans g_chunk/g_loss/g_ticket.
// ---------------------------------------------------------------------------
__global__ void __launch_bounds__(CHKSZ, 1) k_loss(float* __restrict__ out) {
    cudaGridDependencySynchronize();     // PDL: wait for k_scatter completion

    int c    = blockIdx.x / NCHK;
    int ch   = blockIdx.x - c * NCHK;
    int tid  = threadIdx.x;
    int lane = tid & 31;
    int wid  = tid >> 5;

    // chunk totals -> gts and rank-offset
    int k = NCHK - 1 - ch;                           // my bin group
    unsigned long long tot = 0, off = 0;
#pragma unroll
    for (int kk = 0; kk < NCHK; kk++) {
        unsigned long long v = g_chunk[c * NCHK + kk];
        tot += v;
        if (kk > k) off += v;
    }
    long long gts = (long long)(tot >> 32);

    // own bin (rank = ch*128 + tid -> bin), self-clean
    int bin = NBINS - 1 - (ch * CHKSZ + tid);
    unsigned long long mb = g_bins[c * NBINS + bin];
    g_bins[c * NBINS + bin] = 0ULL;

    // block exclusive scan of packed bins (warp shuffle + one smem stage)
    unsigned long long incl = mb;
#pragma unroll
    for (int d = 1; d < 32; d <<= 1) {
        unsigned long long v = __shfl_up_sync(0xffffffffu, incl, d);
        if (lane >= d) incl += v;
    }
    __shared__ unsigned long long wtot[4];
    if (lane == 31) wtot[wid] = incl;
    __syncthreads();
    unsigned long long woff = 0;
#pragma unroll
    for (int ww = 0; ww < 4; ww++)
        if (ww < wid) woff += wtot[ww];
    unsigned long long run = off + woff + incl - mb;     // exclusive prefix

    double acc = 0.0;
    if (gts > 0 && mb) {
        long long n0 = (long long)(unsigned)run;
        long long f0 = (long long)(unsigned)(run >> 32);
        unsigned long long run1 = run + mb;
        long long n1 = (long long)(unsigned)run1;
        long long f1 = (long long)(unsigned)(run1 >> 32);
        long long iv0 = gts - f0, u0 = gts + n0 - f0;
        long long iv1 = gts - f1, u1 = gts + n1 - f1;
        long long num = iv0 * u1 - iv1 * u0;             // exact in int64
        float fnum = (float)num;
        float fden = (float)u0 * (float)u1;
        float e    = ((float)bin + 0.5f) * (1.0f / (float)NBINS);
        acc = (double)(e * __fdividef(fnum, fden));
    }

    // block reduce (double): warp reduce -> smem -> thread 0
    __shared__ double sred[4];
#pragma unroll
    for (int d = 16; d; d >>= 1) acc += __shfl_down_sync(0xffffffffu, acc, d);
    if (lane == 0) sred[wid] = acc;
    __syncthreads();
    if (tid == 0) {
        double a = sred[0] + sred[1] + sred[2] + sred[3];
        if (a != 0.0) atomicAdd(&g_loss[c], a);
        g_gts[c] = gts;                  // all chunk blocks write same value
        __threadfence();
        unsigned tk = atomicAdd(&g_ticket, 1u);
        if (tk == CC * NCHK - 1) {       // last block finalizes + self-cleans
            __threadfence();
            double s = 0.0, np = 0.0;
            for (int kk = 0; kk < CC; kk++) {
                if (g_gts[kk] > 0) { s += g_loss[kk]; np += 1.0; }
            }
            out[0] = (float)(s / (np > 1.0 ? np : 1.0));
            for (int kk = 0; kk < CC; kk++) g_loss[kk] = 0.0;
            for (int kk = 0; kk < NCHUNKS; kk++) g_chunk[kk] = 0ULL;
            g_ticket = 0u;
        }
    }
}

// ---------------------------------------------------------------------------
extern "C" void kernel_launch(void* const* d_in, const int* in_sizes, int n_in,
                              void* d_out, int out_size) {
    const float* input  = (const float*)d_in[0];
    const int*   target = (const int*)d_in[1];
    float*       out    = (float*)d_out;

    // Allow >48KB dynamic shared memory for the privatized histogram.
    cudaFuncSetAttribute(k_scatter, cudaFuncAttributeMaxDynamicSharedMemorySize,
                         SMEM_BYTES);

    k_scatter<<<SCAT_BLOCKS, SCAT_THREADS, SMEM_BYTES>>>(input, target);

    // k_loss with programmatic dependent launch: spins up during k_scatter's
    // tail; device-side cudaGridDependencySynchronize enforces ordering.
    cudaLaunchConfig_t cfg = {};
    cfg.gridDim  = dim3(CC * NCHK, 1, 1);
    cfg.blockDim = dim3(CHKSZ, 1, 1);
    cudaLaunchAttribute attr[1];
    attr[0].id = cudaLaunchAttributeProgrammaticStreamSerialization;
    attr[0].val.programmaticStreamSerializationAllowed = 1;
    cfg.attrs = attr;
    cfg.numAttrs = 1;
    cudaLaunchKernelEx(&cfg, k_loss, out);
}

// round 16
// speedup vs baseline: 20.7419x; 1.0047x over previous
#include <cuda_runtime.h>
#include <cstdint>

// Problem shape (fixed by the dataset)
#define CC    19
#define BATCH 8
#define HH    512
#define WW    512
#define HW    (HH * WW)          // 262144
#define NPIX  (BATCH * HW)       // 2097152
#define NPAIR (NPIX / 2)         // 1048576 pixel pairs

// Histogram-sort: 1024 bins. Deterministic worst-case loss error =
// 0.5/NBINS * sum(lovasz grad <= 1) = 4.9e-4 < 1e-3 tolerance; measured 2.5e-7.
#define NBINS 1024
#define NCHK  8                          // rank-chunks per class
#define CHKSZ (NBINS / NCHK)             // 128 bins per chunk
#define NCHUNKS (CC * NCHK)              // 152

#define SCAT_BLOCKS 148
#define SCAT_THREADS 1024
#define SMEM_BYTES (CC * NBINS * 4)      // 77824 B packed (fg<<16 | cnt) histogram

// Static device scratch (no allocations allowed). Zero at module load;
// the pipeline self-cleans every call so graph replays start clean:
//   g_bins  : zeroed by the k_loss chunk block that owns each bin range
//   g_chunk, g_total, g_np, g_ticket : zeroed by the ticket-elected final block
__device__ unsigned long long g_bins[CC * NBINS];   // packed (fg<<32 | cnt)
__device__ unsigned long long g_chunk[NCHUNKS];     // packed per-bin-group totals
__device__ double             g_total;
__device__ unsigned int       g_np;
__device__ unsigned int       g_ticket;

// ---------------------------------------------------------------------------
// K1: fused softmax + error quantization + SMEM-privatized histogram.
// Pixel-paired float2 loads. fmax guard dropped: cvt.rzi.u32.f32 saturates
// negative (1-p rounding) to bin 0 in hardware. Chunk totals reduced in
// SMEM, ONE widened u64 REDG per (chunk, block). Ends with fence + PDL
// trigger so the dependent k_loss releases at last-CTA-trigger instead of
// kernel teardown.
// ---------------------------------------------------------------------------
__global__ void __launch_bounds__(SCAT_THREADS, 1)
k_scatter(const float* __restrict__ in, const int* __restrict__ tgt) {
    extern __shared__ unsigned int s_cnt[];          // [CC * NBINS]

    for (int i = threadIdx.x; i < CC * NBINS; i += SCAT_THREADS) s_cnt[i] = 0u;
    __syncthreads();

    const int stride = SCAT_BLOCKS * SCAT_THREADS;
    for (int i = blockIdx.x * SCAT_THREADS + threadIdx.x; i < NPAIR; i += stride) {
        int t  = i * 2;                  // even pixel index
        int b  = t >> 18;                // t / HW
        int hw = t & (HW - 1);           // even -> hw+1 < HW
        const float2* base2 =
            reinterpret_cast<const float2*>(in + (size_t)b * CC * HW + hw);

        float x0[CC], x1[CC];
        float s0 = 0.f, s1 = 0.f;
#pragma unroll
        for (int c = 0; c < CC; c++) {
            float2 v = base2[c * (HW / 2)];
            x0[c] = __expf(v.x);         // logits ~N(0,1): no overflow
            x1[c] = __expf(v.y);
            s0 += x0[c];
            s1 += x1[c];
        }
        float inv0 = __fdividef(1.0f, s0);
        float inv1 = __fdividef(1.0f, s1);
        int2 lbl = reinterpret_cast<const int2*>(tgt)[i];

#pragma unroll
        for (int c = 0; c < CC; c++) {
            // pixel 0  (negative e saturates to bin 0 via F2U)
            float p0  = x0[c] * inv0;
            bool  fg0 = (c == lbl.x);
            float e0  = fg0 ? (1.0f - p0) : p0;
            unsigned bin0 = (unsigned)(e0 * (float)NBINS);
            if (bin0 >= NBINS) bin0 = NBINS - 1;
            atomicAdd(&s_cnt[c * NBINS + bin0], 1u + ((unsigned)fg0 << 16));
            // pixel 1
            float p1  = x1[c] * inv1;
            bool  fg1 = (c == lbl.y);
            float e1  = fg1 ? (1.0f - p1) : p1;
            unsigned bin1 = (unsigned)(e1 * (float)NBINS);
            if (bin1 >= NBINS) bin1 = NBINS - 1;
            atomicAdd(&s_cnt[c * NBINS + bin1], 1u + ((unsigned)fg1 << 16));
        }
    }
    __syncthreads();

    // flush nonzero bins into packed u64 global (fg<<32 | cnt)
    for (int i = threadIdx.x; i < CC * NBINS; i += SCAT_THREADS) {
        unsigned v = s_cnt[i];
        if (v) atomicAdd(&g_bins[i],
                 ((unsigned long long)(v >> 16) << 32) |
                  (unsigned long long)(v & 0xFFFFu));
    }

    // per-block chunk totals: warp w handles chunks w, w+32, ...
    // (packed u32 sum overflow-safe: per-block cnt <= 14170 < 2^16,
    //  fg_sum<<16 <= 9.3e8 < 2^32)
    int lane = threadIdx.x & 31;
    int wid  = threadIdx.x >> 5;
    for (int ch = wid; ch < NCHUNKS; ch += 32) {
        const unsigned* p = s_cnt + ch * CHKSZ;
        unsigned sum = 0;
#pragma unroll
        for (int j = 0; j < CHKSZ / 32; j++) sum += p[j * 32 + lane];
#pragma unroll
        for (int d = 16; d; d >>= 1) sum += __shfl_down_sync(0xffffffffu, sum, d);
        if (lane == 0 && sum)
            atomicAdd(&g_chunk[ch],
                      ((unsigned long long)(sum >> 16) << 32) |
                       (unsigned long long)(sum & 0xFFFFu));
    }

    // release the dependent k_loss grid: all writes fenced, then trigger
    __threadfence();
    __syncthreads();
    if (threadIdx.x == 0) cudaTriggerProgrammaticLaunchCompletion();
}

// ---------------------------------------------------------------------------
// K2: grid = CC*NCHK = 152 independent chunk blocks, 128 threads each.
// PDL: cudaGridDependencySynchronize() at entry. Block (c, ch) owns ranks
// [ch*128, (ch+1)*128); rank r -> bin NBINS-1-r. Offset/gts come from the 8
// g_chunk entries, so the block touches ONLY its own 128 raw bins and
// self-cleans them race-free. Exact int64 numerator Lovasz-Jaccard step:
//   j1-j0 = (i0*u1 - i1*u0)/(u0*u1), i = gts-f, u = gts+n-f; num exact in
// int64, all terms >= 0 -> FP32 divide safe; accumulate in double.
// SLIM TAIL: every block atomicAdds into one g_total; ch==0 blocks count
// presence in g_np; ticket-elected last block does 2 loads + 1 divide +
// cleanup (no per-class g_loss/g_gts arrays, no 38-load dependent chain).
// ---------------------------------------------------------------------------
__global__ void __launch_bounds__(CHKSZ, 1) k_loss(float* __restrict__ out) {
    cudaGridDependencySynchronize();     // PDL: wait for k_scatter trigger

    int c    = blockIdx.x / NCHK;
    int ch   = blockIdx.x - c * NCHK;
    int tid  = threadIdx.x;
    int lane = tid & 31;
    int wid  = tid >> 5;

    // chunk totals -> gts and rank-offset
    int k = NCHK - 1 - ch;                           // my bin group
    unsigned long long tot = 0, off = 0;
#pragma unroll
    for (int kk = 0; kk < NCHK; kk++) {
        unsigned long long v = g_chunk[c * NCHK + kk];
        tot += v;
        if (kk > k) off += v;
    }
    long long gts = (long long)(tot >> 32);

    // own bin (rank = ch*128 + tid -> bin), self-clean
    int bin = NBINS - 1 - (ch * CHKSZ + tid);
    unsigned long long mb = g_bins[c * NBINS + bin];
    g_bins[c * NBINS + bin] = 0ULL;

    // block exclusive scan of packed bins (warp shuffle + one smem stage)
    unsigned long long incl = mb;
#pragma unroll
    for (int d = 1; d < 32; d <<= 1) {
        unsigned long long v = __shfl_up_sync(0xffffffffu, incl, d);
        if (lane >= d) incl += v;
    }
    __shared__ unsigned long long wtot[4];
    if (lane == 31) wtot[wid] = incl;
    __syncthreads();
    unsigned long long woff = 0;
#pragma unroll
    for (int ww = 0; ww < 4; ww++)
        if (ww < wid) woff += wtot[ww];
    unsigned long long run = off + woff + incl - mb;     // exclusive prefix

    double acc = 0.0;
    if (gts > 0 && mb) {
        long long n0 = (long long)(unsigned)run;
        long long f0 = (long long)(unsigned)(run >> 32);
        unsigned long long run1 = run + mb;
        long long n1 = (long long)(unsigned)run1;
        long long f1 = (long long)(unsigned)(run1 >> 32);
        long long iv0 = gts - f0, u0 = gts + n0 - f0;
        long long iv1 = gts - f1, u1 = gts + n1 - f1;
        long long num = iv0 * u1 - iv1 * u0;             // exact in int64
        float fnum = (float)num;
        float fden = (float)u0 * (float)u1;
        float e    = ((float)bin + 0.5f) * (1.0f / (float)NBINS);
        acc = (double)(e * __fdividef(fnum, fden));
    }

    // block reduce (double): warp reduce -> smem -> thread 0
    __shared__ double sred[4];
#pragma unroll
    for (int d = 16; d; d >>= 1) acc += __shfl_down_sync(0xffffffffu, acc, d);
    if (lane == 0) sred[wid] = acc;
    __syncthreads();
    if (tid == 0) {
        double a = sred[0] + sred[1] + sred[2] + sred[3];
        if (a != 0.0) atomicAdd(&g_total, a);
        if (ch == 0 && gts > 0) atomicAdd(&g_np, 1u);
        __threadfence();
        unsigned tk = atomicAdd(&g_ticket, 1u);
        if (tk == NCHUNKS - 1) {         // last block finalizes + self-cleans
            __threadfence();
            double s   = g_total;
            unsigned np = g_np;
            out[0] = (float)(s / (np > 1u ? (double)np : 1.0));
            for (int kk = 0; kk < NCHUNKS; kk++) g_chunk[kk] = 0ULL;
            g_total  = 0.0;
            g_np     = 0u;
            g_ticket = 0u;
        }
    }
}

// ---------------------------------------------------------------------------
extern "C" void kernel_launch(void* const* d_in, const int* in_sizes, int n_in,
                              void* d_out, int out_size) {
    const float* input  = (const float*)d_in[0];
    const int*   target = (const int*)d_in[1];
    float*       out    = (float*)d_out;

    // Allow >48KB dynamic shared memory for the privatized histogram.
    cudaFuncSetAttribute(k_scatter, cudaFuncAttributeMaxDynamicSharedMemorySize,
                         SMEM_BYTES);

    k_scatter<<<SCAT_BLOCKS, SCAT_THREADS, SMEM_BYTES>>>(input, target);

    // k_loss with programmatic dependent launch; primary triggers at its end.
    cudaLaunchConfig_t cfg = {};
    cfg.gridDim  = dim3(NCHUNKS, 1, 1);
    cfg.blockDim = dim3(CHKSZ, 1, 1);
    cudaLaunchAttribute attr[1];
    attr[0].id = cudaLaunchAttributeProgrammaticStreamSerialization;
    attr[0].val.programmaticStreamSerializationAllowed = 1;
    cfg.attrs = attr;
    cfg.numAttrs = 1;
    cudaLaunchKernelEx(&cfg, k_loss, out);
}